// round 1
// baseline (speedup 1.0000x reference)
#include <cuda_runtime.h>
#include <math.h>

// Problem constants (fixed-shape problem)
#define Nn   20000
#define Ee   100000
#define Ll   4
#define Dd   64
#define Hh   8
#define HIDc 512

// ---------------- scratch (device globals; no allocation allowed) ----------
__device__ float g_h0[(size_t)Ee * HIDc];   // LSTM hidden ping
__device__ float g_h1[(size_t)Ee * HIDc];   // LSTM hidden pong (final h lives here)
__device__ float g_c [(size_t)Ee * HIDc];   // cell state (in-place per step)
__device__ float g_a [(size_t)Ee * Hh];     // attention logits, then exp values
__device__ float g_amax[(size_t)Nn * Hh];   // segment max (float bits, atomic trick)
__device__ float g_den [(size_t)Nn * Hh];   // segment softmax denominator

// ---------------- init: zero output, reset segment buffers -----------------
__global__ void init_kernel(float* __restrict__ out) {
    int i = blockIdx.x * blockDim.x + threadIdx.x;
    if (i < Nn * HIDc) out[i] = 0.f;
    if (i < Nn * Hh) {
        g_amax[i] = __int_as_float(0xFF800000); // -inf
        g_den[i]  = 0.f;
    }
}

// ---------------- fused LSTM step -------------------------------------------
// gates(E x 2048) = x_t @ W_ih^T + h_prev @ W_hh^T + b, then cell elementwise.
// Tile: BM=64 edge rows, 32 hidden units -> 128 gate columns interleaved as
// col c -> hidden j = c>>2, gate g = c&3  (gate row r = g*512 + h0 + j).
// Each thread: 4 rows x 8 cols = 4 rows x (2 hidden x 4 gates) -> full cell
// update from registers.
__global__ __launch_bounds__(256)
void lstm_step_kernel(const float* __restrict__ feat,
                      const int*   __restrict__ idx,
                      const float* __restrict__ Wih,
                      const float* __restrict__ Whh,
                      const float* __restrict__ bih,
                      const float* __restrict__ bhh,
                      int t)
{
    const int BM = 64, BK = 16;
    __shared__ __align__(16) float As[BK][BM];
    __shared__ __align__(16) float Bs[BK][132];   // 128 cols + pad (row = 528B, 16B-mult)
    __shared__ int rows[BM];

    const float* hprev = (t & 1) ? g_h0 : g_h1;
    float*       hnext = (t & 1) ? g_h1 : g_h0;
    const bool   first = (t == 0);

    int tid = threadIdx.x;
    int e0  = blockIdx.x * BM;
    int h0  = blockIdx.y * 32;

    if (tid < BM) {
        int e = e0 + tid;
        rows[tid] = (e < Ee) ? idx[e * Ll + t] : 0;
    }

    int tx = tid & 15;   // 0..15 -> cols tx*8..tx*8+7
    int ty = tid >> 4;   // 0..15 -> rows ty*4..ty*4+3

    float bias[8];
#pragma unroll
    for (int j = 0; j < 8; j++) {
        int c = tx * 8 + j;
        int r = (c & 3) * HIDc + h0 + (c >> 2);
        bias[j] = bih[r] + bhh[r];
    }

    float acc[4][8];
#pragma unroll
    for (int i = 0; i < 4; i++)
#pragma unroll
        for (int j = 0; j < 8; j++) acc[i][j] = 0.f;

    // loader lane mapping
    int lm = tid >> 2;            // 0..63  A row
    int lk = (tid & 3) * 4;       // 0,4,8,12  A k quad
    int cB = tid >> 1;            // 0..127 B col
    int kq = (tid & 1) * 8;       // 0/8    B k half
    int rB = (cB & 3) * HIDc + h0 + (cB >> 2);

    __syncthreads();   // rows[] visible

    // ---- phase 1: K = D (gathered features) against W_ih ----
    for (int k0 = 0; k0 < Dd; k0 += BK) {
        float4 av = *(const float4*)(feat + (size_t)rows[lm] * Dd + k0 + lk);
        As[lk + 0][lm] = av.x; As[lk + 1][lm] = av.y;
        As[lk + 2][lm] = av.z; As[lk + 3][lm] = av.w;
        const float* wp = Wih + (size_t)rB * Dd + k0 + kq;
        float4 b0 = *(const float4*)(wp);
        float4 b1 = *(const float4*)(wp + 4);
        Bs[kq + 0][cB] = b0.x; Bs[kq + 1][cB] = b0.y;
        Bs[kq + 2][cB] = b0.z; Bs[kq + 3][cB] = b0.w;
        Bs[kq + 4][cB] = b1.x; Bs[kq + 5][cB] = b1.y;
        Bs[kq + 6][cB] = b1.z; Bs[kq + 7][cB] = b1.w;
        __syncthreads();
#pragma unroll
        for (int k = 0; k < BK; k++) {
            float a4[4]; *(float4*)a4 = *(const float4*)&As[k][ty * 4];
            float b8[8];
            *(float4*)(b8)     = *(const float4*)&Bs[k][tx * 8];
            *(float4*)(b8 + 4) = *(const float4*)&Bs[k][tx * 8 + 4];
#pragma unroll
            for (int i = 0; i < 4; i++)
#pragma unroll
                for (int j = 0; j < 8; j++) acc[i][j] += a4[i] * b8[j];
        }
        __syncthreads();
    }

    // ---- phase 2: K = HID (previous hidden) against W_hh ----
    if (!first) {
        int eA = e0 + lm; if (eA >= Ee) eA = Ee - 1;
        const float* hrow = hprev + (size_t)eA * HIDc;
        for (int k0 = 0; k0 < HIDc; k0 += BK) {
            float4 av = *(const float4*)(hrow + k0 + lk);
            As[lk + 0][lm] = av.x; As[lk + 1][lm] = av.y;
            As[lk + 2][lm] = av.z; As[lk + 3][lm] = av.w;
            const float* wp = Whh + (size_t)rB * HIDc + k0 + kq;
            float4 b0 = *(const float4*)(wp);
            float4 b1 = *(const float4*)(wp + 4);
            Bs[kq + 0][cB] = b0.x; Bs[kq + 1][cB] = b0.y;
            Bs[kq + 2][cB] = b0.z; Bs[kq + 3][cB] = b0.w;
            Bs[kq + 4][cB] = b1.x; Bs[kq + 5][cB] = b1.y;
            Bs[kq + 6][cB] = b1.z; Bs[kq + 7][cB] = b1.w;
            __syncthreads();
#pragma unroll
            for (int k = 0; k < BK; k++) {
                float a4[4]; *(float4*)a4 = *(const float4*)&As[k][ty * 4];
                float b8[8];
                *(float4*)(b8)     = *(const float4*)&Bs[k][tx * 8];
                *(float4*)(b8 + 4) = *(const float4*)&Bs[k][tx * 8 + 4];
#pragma unroll
                for (int i = 0; i < 4; i++)
#pragma unroll
                    for (int j = 0; j < 8; j++) acc[i][j] += a4[i] * b8[j];
            }
            __syncthreads();
        }
    }

    // ---- epilogue: LSTM cell from registers ----
#pragma unroll
    for (int i = 0; i < 4; i++) {
        int e = e0 + ty * 4 + i;
        if (e >= Ee) continue;
#pragma unroll
        for (int u = 0; u < 2; u++) {
            int jh = tx * 2 + u;
            float gi = acc[i][u * 4 + 0] + bias[u * 4 + 0];
            float gf = acc[i][u * 4 + 1] + bias[u * 4 + 1];
            float gg = acc[i][u * 4 + 2] + bias[u * 4 + 2];
            float go = acc[i][u * 4 + 3] + bias[u * 4 + 3];
            float si = 1.f / (1.f + __expf(-gi));
            float sf = 1.f / (1.f + __expf(-gf));
            float tg = tanhf(gg);
            float so = 1.f / (1.f + __expf(-go));
            size_t cix = (size_t)e * HIDc + h0 + jh;
            float cold = first ? 0.f : g_c[cix];
            float cn = sf * cold + si * tg;
            g_c[cix]   = cn;
            hnext[cix] = so * tanhf(cn);
        }
    }
}

// ---------------- attention logits + segment max (warp per edge) -----------
__global__ void attn_logits_kernel(const float* __restrict__ feat,
                                   const int*   __restrict__ idx,
                                   const int*   __restrict__ dst,
                                   const float* __restrict__ attn1w,
                                   const float* __restrict__ attn2)
{
    int warp = (blockIdx.x * blockDim.x + threadIdx.x) >> 5;
    int lane = threadIdx.x & 31;
    if (warp >= Ee) return;
    const float* hlast = g_h1;   // final hidden after t=3

    int h   = lane >> 2;   // head 0..7
    int seg = lane & 3;    // k-quarter

    const float* eft = hlast + (size_t)warp * HIDc + h * Dd;
    const float* w2  = attn2  + h * Dd;
    int cidx = idx[warp * Ll + (Ll - 1)];
    const float* ctr = feat + (size_t)cidx * Dd;
    const float* w1  = attn1w + h * Dd;

    float s = 0.f;
#pragma unroll
    for (int q = 0; q < 4; q++) {
        int o = seg * 16 + q * 4;
        float4 ev = *(const float4*)(eft + o);
        float4 wv = *(const float4*)(w2 + o);
        float4 cv = *(const float4*)(ctr + o);
        float4 av = *(const float4*)(w1 + o);
        s += ev.x * wv.x + ev.y * wv.y + ev.z * wv.z + ev.w * wv.w;
        s += cv.x * av.x + cv.y * av.y + cv.z * av.z + cv.w * av.w;
    }
    s += __shfl_down_sync(0xffffffffu, s, 2);
    s += __shfl_down_sync(0xffffffffu, s, 1);

    if (seg == 0) {
        float a = (s > 0.f) ? s : 0.01f * s;   // leaky_relu(0.01)
        g_a[(size_t)warp * Hh + h] = a;
        float* addr = &g_amax[(size_t)dst[warp] * Hh + h];
        if (a >= 0.f) atomicMax((int*)addr, __float_as_int(a));
        else          atomicMin((unsigned int*)addr, __float_as_uint(a));
    }
}

// ---------------- exp + denominator -----------------------------------------
__global__ void softmax_norm_kernel(const int* __restrict__ dst) {
    int i = blockIdx.x * blockDim.x + threadIdx.x;
    if (i >= Ee * Hh) return;
    int e = i >> 3, h = i & 7;
    int d = dst[e];
    float ex = __expf(g_a[i] - g_amax[(size_t)d * Hh + h]);
    g_a[i] = ex;
    atomicAdd(&g_den[(size_t)d * Hh + h], ex);
}

// ---------------- weighted segment scatter ----------------------------------
__global__ void scatter_out_kernel(const int* __restrict__ dst,
                                   float* __restrict__ out) {
    int i = blockIdx.x * blockDim.x + threadIdx.x;   // over E*512
    if (i >= Ee * HIDc) return;
    int e = i >> 9, col = i & 511, h = col >> 6;
    int d = dst[e];
    float w = g_a[(size_t)e * Hh + h] / g_den[(size_t)d * Hh + h];
    atomicAdd(out + (size_t)d * HIDc + col, g_h1[i] * w);
}

// ---------------- launch ------------------------------------------------------
extern "C" void kernel_launch(void* const* d_in, const int* in_sizes, int n_in,
                              void* d_out, int out_size)
{
    const float* feat = (const float*)d_in[0];
    // d_in[1] = type_mask (unused by reference)
    const int*   idx  = (const int*)d_in[2];
    const int*   dst  = (const int*)d_in[3];
    const float* Wih  = (const float*)d_in[4];
    const float* Whh  = (const float*)d_in[5];
    const float* bih  = (const float*)d_in[6];
    const float* bhh  = (const float*)d_in[7];
    const float* a1w  = (const float*)d_in[8];
    const float* a2w  = (const float*)d_in[9];
    float* out = (float*)d_out;

    init_kernel<<<(Nn * HIDc + 255) / 256, 256>>>(out);

    dim3 lgrid((Ee + 63) / 64, HIDc / 32);
    for (int t = 0; t < Ll; t++)
        lstm_step_kernel<<<lgrid, 256>>>(feat, idx, Wih, Whh, bih, bhh, t);

    attn_logits_kernel<<<(Ee * 32 + 255) / 256, 256>>>(feat, idx, dst, a1w, a2w);
    softmax_norm_kernel<<<(Ee * Hh + 255) / 256, 256>>>(dst);
    scatter_out_kernel<<<(Ee * HIDc + 255) / 256, 256>>>(dst, out);
}

// round 3
// speedup vs baseline: 2.2352x; 2.2352x over previous
#include <cuda_runtime.h>
#include <math.h>
#include <stdint.h>

// Problem constants (fixed-shape problem)
#define Nn   20000
#define Ee   100000
#define Ll   4
#define Dd   64
#define Hh   8
#define HIDc 512

// mma.sync tf32 LSTM tiling
#define BM   128        // edges per CTA
#define BNH  32         // hidden units per CTA -> 128 gate columns
#define BK   32         // K per chunk
#define LDSW 36         // smem row stride in words (32 + 4 pad: conflict-free frags)
#define TILE_WORDS (BM * LDSW)                 // 4608
#define DYN_SMEM   (4 * TILE_WORDS * 4)       // 2 bufs x (A+B) = 73728 B

// ---------------- scratch (device globals; no allocation allowed) ----------
__device__ float g_h0[(size_t)Ee * HIDc];
__device__ float g_h1[(size_t)Ee * HIDc];
__device__ float g_c [(size_t)Ee * HIDc];
__device__ float g_a [(size_t)Ee * Hh];
__device__ float g_amax[(size_t)Nn * Hh];
__device__ float g_den [(size_t)Nn * Hh];

// ---------------- helpers ----------------------------------------------------
__device__ __forceinline__ uint32_t f2tf(float f) {
    uint32_t r;
    asm("cvt.rna.tf32.f32 %0, %1;" : "=r"(r) : "f"(f));
    return r;
}
__device__ __forceinline__ void mma8(float* d, const uint32_t* a,
                                     uint32_t b0, uint32_t b1) {
    asm volatile(
        "mma.sync.aligned.m16n8k8.row.col.f32.tf32.tf32.f32 "
        "{%0,%1,%2,%3}, {%4,%5,%6,%7}, {%8,%9}, {%0,%1,%2,%3};"
        : "+f"(d[0]), "+f"(d[1]), "+f"(d[2]), "+f"(d[3])
        : "r"(a[0]), "r"(a[1]), "r"(a[2]), "r"(a[3]), "r"(b0), "r"(b1));
}

// ---------------- init -------------------------------------------------------
__global__ void init_kernel(float* __restrict__ out) {
    int i = blockIdx.x * blockDim.x + threadIdx.x;
    if (i < Nn * HIDc) out[i] = 0.f;
    if (i < Nn * Hh) {
        g_amax[i] = __int_as_float(0xFF800000);
        g_den[i]  = 0.f;
    }
}

// ---------------- tensor-core (mma.sync tf32) LSTM step ----------------------
// gates(E x 2048) = x_t @ W_ih^T + h_prev @ W_hh^T (+bias in epilogue).
// CTA: 128 edges x 32 hidden (x4 gates = 128 gate cols), K double-buffered by 32.
// Warp (8 warps: 4 along M x 2 along Nh): 32 rows x 16 hidden x 4 gates.
// B smem column c = gate(c>>5)*32 + local_hidden(c&31); weight row = g*512+hid.
__global__ __launch_bounds__(256, 1)
void lstm_mma_kernel(const float* __restrict__ feat,
                     const int*   __restrict__ idx,
                     const float* __restrict__ Wih,
                     const float* __restrict__ Whh,
                     const float* __restrict__ bih,
                     const float* __restrict__ bhh,
                     int t)
{
    extern __shared__ uint32_t smem[];
    __shared__ int   rows_s[BM];
    __shared__ float bias_s[128];

    const int tid   = threadIdx.x;
    const int wid   = tid >> 5;
    const int lane  = tid & 31;
    const int warpM = wid & 3;        // 0..3 (rows)
    const int warpN = wid >> 2;       // 0..1 (hidden halves)
    const int e0    = blockIdx.x * BM;
    const int nh0   = blockIdx.y * BNH;

    const float* hprev = (t & 1) ? g_h0 : g_h1;
    float*       hnext = (t & 1) ? g_h1 : g_h0;
    const bool   first = (t == 0);
    const int    NC    = first ? 2 : 18;      // K chunks: 64 feat (+512 hidden)

    // shared init
    if (tid < BM) {
        int e = e0 + tid; if (e >= Ee) e = Ee - 1;
        rows_s[tid] = idx[e * Ll + t];
    }
    if (tid < 128) {   // bias, c = g*32 + hh
        int g = tid >> 5, hh = tid & 31;
        int r = g * HIDc + nh0 + hh;
        bias_s[tid] = bih[r] + bhh[r];
    }

    // fill-lane mapping: row r, k-half kh (16 floats = 4 float4 each for A and B)
    const int r     = tid & 127;
    const int kh    = (tid >> 7) & 1;
    const int k0loc = kh * 16;
    const int bg    = r >> 5, bhh_ = r & 31;
    const int wrow  = bg * HIDc + nh0 + bhh_;

    float4 va[4], vb[4];
    auto load_regs = [&](int kc) {
        const float* ap;
        if (kc < 2) {
            ap = feat + (size_t)rows_s[r] * Dd + kc * BK + k0loc;
        } else {
            int e = e0 + r; if (e >= Ee) e = Ee - 1;
            ap = hprev + (size_t)e * HIDc + (kc - 2) * BK + k0loc;
        }
        const float* bp = (kc < 2)
            ? Wih + (size_t)wrow * Dd   + kc * BK + k0loc
            : Whh + (size_t)wrow * HIDc + (kc - 2) * BK + k0loc;
#pragma unroll
        for (int q = 0; q < 4; q++) {
            va[q] = __ldg((const float4*)(ap) + q);
            vb[q] = __ldg((const float4*)(bp) + q);
        }
    };
    auto store_stage = [&](int buf) {
        uint32_t* da = smem + buf * TILE_WORDS + r * LDSW + k0loc;
        uint32_t* db = da + 2 * TILE_WORDS;
#pragma unroll
        for (int q = 0; q < 4; q++) {
            uint4 ua = make_uint4(f2tf(va[q].x), f2tf(va[q].y), f2tf(va[q].z), f2tf(va[q].w));
            uint4 ub = make_uint4(f2tf(vb[q].x), f2tf(vb[q].y), f2tf(vb[q].z), f2tf(vb[q].w));
            *(uint4*)(da + q * 4) = ua;
            *(uint4*)(db + q * 4) = ub;
        }
    };

    float acc[2][2][4][4];
#pragma unroll
    for (int mb = 0; mb < 2; mb++)
#pragma unroll
        for (int nb = 0; nb < 2; nb++)
#pragma unroll
            for (int g = 0; g < 4; g++)
#pragma unroll
                for (int v = 0; v < 4; v++) acc[mb][nb][g][v] = 0.f;

    __syncthreads();                 // rows_s ready
    load_regs(0);
    store_stage(0);
    __syncthreads();

    const int arow = warpM * 32 + (lane >> 2);
    const int kl   = lane & 3;

    for (int kc = 0; kc < NC; kc++) {
        const int buf = kc & 1;
        if (kc + 1 < NC) load_regs(kc + 1);

        const uint32_t* Ab = smem + buf * TILE_WORDS;
        const uint32_t* Bb = Ab + 2 * TILE_WORDS;
#pragma unroll
        for (int kk = 0; kk < 4; kk++) {
            uint32_t afr[2][4];
#pragma unroll
            for (int mb = 0; mb < 2; mb++) {
                const uint32_t* A0 = Ab + (arow + mb * 16) * LDSW + kk * 8 + kl;
                afr[mb][0] = A0[0];
                afr[mb][1] = A0[8 * LDSW];
                afr[mb][2] = A0[4];
                afr[mb][3] = A0[8 * LDSW + 4];
            }
#pragma unroll
            for (int nb = 0; nb < 2; nb++) {
                int colb = warpN * 16 + nb * 8 + (lane >> 2);
#pragma unroll
                for (int g = 0; g < 4; g++) {
                    const uint32_t* B0 = Bb + (g * 32 + colb) * LDSW + kk * 8 + kl;
                    uint32_t b0 = B0[0], b1 = B0[4];
                    mma8(acc[0][nb][g], afr[0], b0, b1);
                    mma8(acc[1][nb][g], afr[1], b0, b1);
                }
            }
        }
        if (kc + 1 < NC) {
            __syncthreads();
            store_stage((kc + 1) & 1);
            __syncthreads();
        }
    }

    // ---- epilogue: LSTM cell from accumulators ------------------------------
#pragma unroll
    for (int mb = 0; mb < 2; mb++) {
#pragma unroll
        for (int rh = 0; rh < 2; rh++) {
            int e = e0 + warpM * 32 + mb * 16 + (lane >> 2) + rh * 8;
            if (e >= Ee) continue;
            float* cp = g_c   + (size_t)e * HIDc + nh0;
            float* hp = hnext + (size_t)e * HIDc + nh0;
#pragma unroll
            for (int nb = 0; nb < 2; nb++) {
                int hh = warpN * 16 + nb * 8 + (lane & 3) * 2;
                float2 cold = make_float2(0.f, 0.f);
                if (!first) cold = *(const float2*)(cp + hh);
                float cv[2], hv[2];
#pragma unroll
                for (int v = 0; v < 2; v++) {
                    int ci = rh * 2 + v;
                    float gi = acc[mb][nb][0][ci] + bias_s[      hh + v];
                    float gf = acc[mb][nb][1][ci] + bias_s[ 32 + hh + v];
                    float gg = acc[mb][nb][2][ci] + bias_s[ 64 + hh + v];
                    float go = acc[mb][nb][3][ci] + bias_s[ 96 + hh + v];
                    float si = 1.f / (1.f + __expf(-gi));
                    float sf = 1.f / (1.f + __expf(-gf));
                    float tg = tanhf(gg);
                    float so = 1.f / (1.f + __expf(-go));
                    float co = v ? cold.y : cold.x;
                    float cn = sf * co + si * tg;
                    cv[v] = cn;
                    hv[v] = so * tanhf(cn);
                }
                *(float2*)(cp + hh) = make_float2(cv[0], cv[1]);
                *(float2*)(hp + hh) = make_float2(hv[0], hv[1]);
            }
        }
    }
}

// ---------------- attention logits + segment max (warp per edge) -----------
__global__ void attn_logits_kernel(const float* __restrict__ feat,
                                   const int*   __restrict__ idx,
                                   const int*   __restrict__ dst,
                                   const float* __restrict__ attn1w,
                                   const float* __restrict__ attn2)
{
    int warp = (blockIdx.x * blockDim.x + threadIdx.x) >> 5;
    int lane = threadIdx.x & 31;
    if (warp >= Ee) return;
    const float* hlast = g_h1;

    int h   = lane >> 2;
    int seg = lane & 3;

    const float* eft = hlast + (size_t)warp * HIDc + h * Dd;
    const float* w2  = attn2  + h * Dd;
    int cidx = idx[warp * Ll + (Ll - 1)];
    const float* ctr = feat + (size_t)cidx * Dd;
    const float* w1  = attn1w + h * Dd;

    float s = 0.f;
#pragma unroll
    for (int q = 0; q < 4; q++) {
        int o = seg * 16 + q * 4;
        float4 ev = *(const float4*)(eft + o);
        float4 wv = *(const float4*)(w2 + o);
        float4 cv = *(const float4*)(ctr + o);
        float4 av = *(const float4*)(w1 + o);
        s += ev.x * wv.x + ev.y * wv.y + ev.z * wv.z + ev.w * wv.w;
        s += cv.x * av.x + cv.y * av.y + cv.z * av.z + cv.w * av.w;
    }
    s += __shfl_down_sync(0xffffffffu, s, 2);
    s += __shfl_down_sync(0xffffffffu, s, 1);

    if (seg == 0) {
        float a = (s > 0.f) ? s : 0.01f * s;
        g_a[(size_t)warp * Hh + h] = a;
        float* addr = &g_amax[(size_t)dst[warp] * Hh + h];
        if (a >= 0.f) atomicMax((int*)addr, __float_as_int(a));
        else          atomicMin((unsigned int*)addr, __float_as_uint(a));
    }
}

// ---------------- exp + denominator -----------------------------------------
__global__ void softmax_norm_kernel(const int* __restrict__ dst) {
    int i = blockIdx.x * blockDim.x + threadIdx.x;
    if (i >= Ee * Hh) return;
    int e = i >> 3, h = i & 7;
    int d = dst[e];
    float ex = __expf(g_a[i] - g_amax[(size_t)d * Hh + h]);
    g_a[i] = ex;
    atomicAdd(&g_den[(size_t)d * Hh + h], ex);
}

// ---------------- weighted segment scatter ----------------------------------
__global__ void scatter_out_kernel(const int* __restrict__ dst,
                                   float* __restrict__ out) {
    int i = blockIdx.x * blockDim.x + threadIdx.x;
    if (i >= Ee * HIDc) return;
    int e = i >> 9, col = i & 511, h = col >> 6;
    int d = dst[e];
    float w = g_a[(size_t)e * Hh + h] / g_den[(size_t)d * Hh + h];
    atomicAdd(out + (size_t)d * HIDc + col, g_h1[i] * w);
}

// ---------------- launch ------------------------------------------------------
extern "C" void kernel_launch(void* const* d_in, const int* in_sizes, int n_in,
                              void* d_out, int out_size)
{
    const float* feat = (const float*)d_in[0];
    const int*   idx  = (const int*)d_in[2];
    const int*   dst  = (const int*)d_in[3];
    const float* Wih  = (const float*)d_in[4];
    const float* Whh  = (const float*)d_in[5];
    const float* bih  = (const float*)d_in[6];
    const float* bhh  = (const float*)d_in[7];
    const float* a1w  = (const float*)d_in[8];
    const float* a2w  = (const float*)d_in[9];
    float* out = (float*)d_out;

    cudaFuncSetAttribute(lstm_mma_kernel,
                         cudaFuncAttributeMaxDynamicSharedMemorySize, DYN_SMEM);

    init_kernel<<<(Nn * HIDc + 255) / 256, 256>>>(out);

    dim3 lgrid((Ee + BM - 1) / BM, HIDc / BNH);   // 782 x 16
    for (int t = 0; t < Ll; t++)
        lstm_mma_kernel<<<lgrid, 256, DYN_SMEM>>>(feat, idx, Wih, Whh, bih, bhh, t);

    attn_logits_kernel<<<(Ee * 32 + 255) / 256, 256>>>(feat, idx, dst, a1w, a2w);
    softmax_norm_kernel<<<(Ee * Hh + 255) / 256, 256>>>(dst);
    scatter_out_kernel<<<(Ee * HIDc + 255) / 256, 256>>>(dst, out);
}